// round 1
// baseline (speedup 1.0000x reference)
#include <cuda_runtime.h>

// LIF recurrence: v_t = (v_{t-1} + x_t) * 0.5 ; s_t = sigmoid(v_t - 1) ; v_t *= (1 - s_t)
// x: [B=32, T=512, D=2048] fp32. One thread per (b, d) chain, sequential over t.
// Memory-bound streaming kernel: 256 MB total traffic, ~42 us HBM floor.

#define LIF_B 32
#define LIF_T 512
#define LIF_D 2048
#define LIF_TAU_INV 0.5f
#define LIF_TH 1.0f
#define UNROLL 8

__global__ void __launch_bounds__(128, 16)
lif_kernel(const float* __restrict__ x, float* __restrict__ out) {
    const int gid = blockIdx.x * blockDim.x + threadIdx.x;   // [0, B*D)
    const int b = gid >> 11;          // D = 2048 = 2^11
    const int d = gid & (LIF_D - 1);

    const int base = b * (LIF_T * LIF_D) + d;
    const float* __restrict__ xp = x + base;
    float* __restrict__ op = out + base;

    float v = 0.0f;

    // Outer loop NOT unrolled (keep I$ small); inner block of 8 gives
    // 8 front-batched independent LDGs per warp -> ~2 MB in flight chip-wide.
    for (int t0 = 0; t0 < LIF_T; t0 += UNROLL) {
        float xv[UNROLL];
        #pragma unroll
        for (int u = 0; u < UNROLL; u++) {
            xv[u] = __ldcs(xp + (t0 + u) * LIF_D);   // streaming load, no reuse
        }
        #pragma unroll
        for (int u = 0; u < UNROLL; u++) {
            // leak: v += (x - v)/tau  with tau=2  ->  v = 0.5*(v + x)
            v = (v + xv[u]) * LIF_TAU_INV;
            // surrogate spike: s = sigmoid(v - th) = 1 / (1 + exp(th - v))
            float e = __expf(LIF_TH - v);
            float s = __fdividef(1.0f, 1.0f + e);
            __stcs(op + (t0 + u) * LIF_D, s);        // streaming store
            // soft reset: v = v * (1 - s) = v - v*s
            v = fmaf(-v, s, v);
        }
    }
}

extern "C" void kernel_launch(void* const* d_in, const int* in_sizes, int n_in,
                              void* d_out, int out_size) {
    const float* x = (const float*)d_in[0];
    float* out = (float*)d_out;

    const int n_chains = LIF_B * LIF_D;     // 65536 threads
    const int threads = 128;
    const int blocks = n_chains / threads;  // 512 blocks
    lif_kernel<<<blocks, threads>>>(x, out);
}

// round 2
// speedup vs baseline: 1.5440x; 1.5440x over previous
#include <cuda_runtime.h>

// LIF recurrence: v_t = 0.5*(v_{t-1} + x_t) ; s_t = sigmoid(v_t - 1) ; v_t *= (1 - s_t)
// x: [B=32, T=512, D=2048] fp32. One thread per (b, d) chain, sequential over t.
// Latency-bound fix: explicit double-buffered prefetch, depth 16.
// 2048 warps x 16 x 128B = 4 MB continuously in flight -> HBM saturation.

#define LIF_B 32
#define LIF_T 512
#define LIF_D 2048
#define LIF_TH 1.0f
#define UNROLL 16

__global__ void __launch_bounds__(128, 16)
lif_kernel(const float* __restrict__ x, float* __restrict__ out) {
    const int gid = blockIdx.x * blockDim.x + threadIdx.x;   // [0, B*D)
    const int b = gid >> 11;          // D = 2048 = 2^11
    const int d = gid & (LIF_D - 1);

    const int base = b * (LIF_T * LIF_D) + d;
    const float* __restrict__ xp = x + base;
    float* __restrict__ op = out + base;

    float v = 0.0f;
    float cur[UNROLL], nxt[UNROLL];

    // Prime the pipeline: batch 0.
    #pragma unroll
    for (int u = 0; u < UNROLL; u++) {
        cur[u] = __ldcs(xp + u * LIF_D);
    }

    for (int t0 = 0; t0 < LIF_T; t0 += UNROLL) {
        // 1) Prefetch next batch FIRST — these 16 independent LDGs go into
        //    flight while we chew through the serial compute chain below.
        const int tn = t0 + UNROLL;
        const bool has_next = (tn < LIF_T);
        #pragma unroll
        for (int u = 0; u < UNROLL; u++) {
            nxt[u] = has_next ? __ldcs(xp + (tn + u) * LIF_D) : 0.0f;
        }

        // 2) Compute current batch (serial v-dependency, ~48 cyc/t).
        #pragma unroll
        for (int u = 0; u < UNROLL; u++) {
            const float xh = 0.5f * cur[u];          // off critical path
            v = fmaf(0.5f, v, xh);                   // leak (4-cyc chain step)
            // s = sigmoid(v - th) = 1 / (1 + exp(th - v))
            const float e = __expf(LIF_TH - v);
            const float s = __fdividef(1.0f, 1.0f + e);
            __stcs(op + (t0 + u) * LIF_D, s);        // streaming store
            v = fmaf(-v, s, v);                      // soft reset v*(1-s)
        }

        // 3) Rotate buffers (register moves, zero memory traffic).
        #pragma unroll
        for (int u = 0; u < UNROLL; u++) {
            cur[u] = nxt[u];
        }
    }
}

extern "C" void kernel_launch(void* const* d_in, const int* in_sizes, int n_in,
                              void* d_out, int out_size) {
    const float* x = (const float*)d_in[0];
    float* out = (float*)d_out;

    const int n_chains = LIF_B * LIF_D;     // 65536 threads
    const int threads = 128;
    const int blocks = n_chains / threads;  // 512 blocks
    lif_kernel<<<blocks, threads>>>(x, out);
}

// round 3
// speedup vs baseline: 1.9109x; 1.2376x over previous
#include <cuda_runtime.h>

// LIF recurrence over T, chunked: the recurrence contracts (|dv_t/dv_{t-1}| <~ 0.55),
// so each 128-step chunk can start from v=0 with a 24-step discarded warmup;
// initial-state error decays to ~2e-7 << 1e-3 tolerance.
// 4x parallelism: 262,144 threads (55 warps/SM) -> TLP covers memory latency.

#define LIF_B 32
#define LIF_T 512
#define LIF_D 2048
#define NCHUNK 4
#define CLEN 128          // LIF_T / NCHUNK
#define WARM 24           // discarded warmup steps (multiple of UN)
#define LIF_TH 1.0f
#define UN 8

__global__ void __launch_bounds__(256)
lif_kernel(const float* __restrict__ x, float* __restrict__ out) {
    const int gid = blockIdx.x * blockDim.x + threadIdx.x;
    const int d  = gid & (LIF_D - 1);          // consecutive threads -> consecutive d
    const int bc = gid >> 11;                  // D = 2^11
    const int c  = bc & (NCHUNK - 1);
    const int b  = bc >> 2;                    // NCHUNK = 2^2

    const size_t base = (size_t)b * LIF_T * LIF_D + d;
    const float* __restrict__ xp = x + base;
    float* __restrict__ op = out + base;

    float v = 0.0f;
    const int t_out0 = c * CLEN;

    // ---- Warmup: run recurrence on the 24 steps before this chunk, no stores.
    // Chunk 0 starts from the true initial state v=0 -> skip. (c is uniform
    // within a warp, so this branch does not diverge.)
    if (c != 0) {
        const int tw0 = t_out0 - WARM;
        #pragma unroll
        for (int tb = 0; tb < WARM; tb += UN) {
            float xv[UN];
            #pragma unroll
            for (int u = 0; u < UN; u++)
                xv[u] = __ldg(xp + (size_t)(tw0 + tb + u) * LIF_D);  // likely L2 hit
            #pragma unroll
            for (int u = 0; u < UN; u++) {
                v = fmaf(0.5f, v, 0.5f * xv[u]);            // leak (tau=2)
                const float e = __expf(LIF_TH - v);
                const float s = __fdividef(1.0f, 1.0f + e); // sigmoid(v - th)
                v = fmaf(-v, s, v);                          // soft reset
            }
        }
    }

    // ---- Main: 128 steps with stores, front-batched loads (8 in flight).
    for (int tb = 0; tb < CLEN; tb += UN) {
        const int t0 = t_out0 + tb;
        float xv[UN];
        #pragma unroll
        for (int u = 0; u < UN; u++)
            xv[u] = __ldcs(xp + (size_t)(t0 + u) * LIF_D);   // streaming read
        #pragma unroll
        for (int u = 0; u < UN; u++) {
            v = fmaf(0.5f, v, 0.5f * xv[u]);
            const float e = __expf(LIF_TH - v);
            const float s = __fdividef(1.0f, 1.0f + e);
            __stcs(op + (size_t)(t0 + u) * LIF_D, s);        // streaming write
            v = fmaf(-v, s, v);
        }
    }
}

extern "C" void kernel_launch(void* const* d_in, const int* in_sizes, int n_in,
                              void* d_out, int out_size) {
    const float* x = (const float*)d_in[0];
    float* out = (float*)d_out;

    const int n_threads_total = LIF_B * LIF_D * NCHUNK;   // 262,144
    const int threads = 256;
    const int blocks = n_threads_total / threads;         // 1024
    lif_kernel<<<blocks, threads>>>(x, out);
}

// round 7
// speedup vs baseline: 1.9156x; 1.0025x over previous
#include <cuda_runtime.h>

// LIF recurrence, chunked 4x over T (24-step discarded warmup; recurrence
// contracts at ~0.55/step so chunk-seam error ~1e-6, measured rel_err
// identical to unchunked). This round: explicit double-buffered prefetch
// inside the chunk so loads stay continuously in flight (R3 had none:
// regs=22, DRAM 61.5%). UN=4 keeps regs <= 32 -> full 2048 thr/SM.

#define LIF_B 32
#define LIF_T 512
#define LIF_D 2048
#define NCHUNK 4
#define CLEN 128          // LIF_T / NCHUNK
#define WARM 24           // discarded warmup steps
#define LIF_TH 1.0f
#define UN 4              // main-loop batch (double-buffered)
#define WUN 8             // warmup batch (single-buffered)

__global__ void __launch_bounds__(256, 8)
lif_kernel(const float* __restrict__ x, float* __restrict__ out) {
    const int gid = blockIdx.x * blockDim.x + threadIdx.x;
    const int d  = gid & (LIF_D - 1);          // consecutive threads -> consecutive d
    const int bc = gid >> 11;                  // D = 2^11
    const int c  = bc & (NCHUNK - 1);
    const int b  = bc >> 2;                    // NCHUNK = 2^2

    const size_t base = (size_t)b * LIF_T * LIF_D + d;
    const float* __restrict__ xp = x + base;
    float* __restrict__ op = out + base;

    float v = 0.0f;
    const int t_out0 = c * CLEN;

    // ---- Warmup (chunks 1..3): 24 steps before the chunk, no stores.
    // c is warp-uniform -> no divergence. Reads mostly L2-hit (neighbor
    // chunk streams the same lines concurrently).
    if (c != 0) {
        const int tw0 = t_out0 - WARM;
        #pragma unroll
        for (int tb = 0; tb < WARM; tb += WUN) {
            float xv[WUN];
            #pragma unroll
            for (int u = 0; u < WUN; u++)
                xv[u] = __ldg(xp + (size_t)(tw0 + tb + u) * LIF_D);
            #pragma unroll
            for (int u = 0; u < WUN; u++) {
                v = fmaf(0.5f, v, 0.5f * xv[u]);            // leak (tau=2)
                const float e = __expf(LIF_TH - v);
                const float s = __fdividef(1.0f, 1.0f + e); // sigmoid(v - th)
                v = fmaf(-v, s, v);                          // soft reset
            }
        }
    }

    // ---- Main: 128 steps, double-buffered prefetch (loads always in flight).
    float cur[UN], nxt[UN];
    #pragma unroll
    for (int u = 0; u < UN; u++)
        cur[u] = __ldg(xp + (size_t)(t_out0 + u) * LIF_D);

    for (int tb = 0; tb < CLEN; tb += UN) {
        const int t0 = t_out0 + tb;

        // 1) Prefetch next batch before touching the serial chain.
        //    Predicated: last batch of the last chunk must not read past x.
        const bool has_next = (tb + UN < CLEN);
        #pragma unroll
        for (int u = 0; u < UN; u++)
            nxt[u] = has_next ? __ldg(xp + (size_t)(t0 + UN + u) * LIF_D) : 0.0f;

        // 2) Compute current batch.
        #pragma unroll
        for (int u = 0; u < UN; u++) {
            v = fmaf(0.5f, v, 0.5f * cur[u]);
            const float e = __expf(LIF_TH - v);
            const float s = __fdividef(1.0f, 1.0f + e);
            __stcs(op + (size_t)(t0 + u) * LIF_D, s);       // streaming write
            v = fmaf(-v, s, v);
        }

        // 3) Rotate (register moves only).
        #pragma unroll
        for (int u = 0; u < UN; u++)
            cur[u] = nxt[u];
    }
}

extern "C" void kernel_launch(void* const* d_in, const int* in_sizes, int n_in,
                              void* d_out, int out_size) {
    const float* x = (const float*)d_in[0];
    float* out = (float*)d_out;

    const int n_threads_total = LIF_B * LIF_D * NCHUNK;   // 262,144
    const int threads = 256;
    const int blocks = n_threads_total / threads;         // 1024
    lif_kernel<<<blocks, threads>>>(x, out);
}

// round 12
// speedup vs baseline: 1.9240x; 1.0044x over previous
#include <cuda_runtime.h>

// LIF recurrence, chunked 4x over T with BALANCED chunk lengths:
//   chunk 0: stores t in [0,140)          (no warmup; v=0 is exact)
//   chunk c: stores t in [124c+16, 124c+140), 16-step discarded warmup from 124c
// Every thread executes exactly 140 recurrence steps (R7 had 128 vs 152 ->
// 19% straggler tail). Contraction ~0.53/step => seam error ~3e-5 << 1e-3.
// Triple-buffered prefetch (distance 2) keeps ~8 LDGs/warp continuously in
// flight to lift DRAM past the 67% plateau.

#define LIF_B 32
#define LIF_T 512
#define LIF_D 2048
#define NCHUNK 4
#define WARM 16
#define LEN0 140          // chunk-0 stored length
#define LENC 124          // chunk 1..3 stored length  (140 = 124 + 16 warm)
#define LIF_TH 1.0f
#define UN 4

__device__ __forceinline__ float lif_step(float v, float xin) {
    v = fmaf(0.5f, v, 0.5f * xin);               // leak, tau = 2
    const float e = __expf(LIF_TH - v);
    const float s = __fdividef(1.0f, 1.0f + e);  // sigmoid(v - th)
    // caller stores s when needed
    return fmaf(-v, s, v);                        // soft reset v*(1-s)
}

__global__ void __launch_bounds__(256, 7)
lif_kernel(const float* __restrict__ x, float* __restrict__ out) {
    const int gid = blockIdx.x * blockDim.x + threadIdx.x;
    const int d  = gid & (LIF_D - 1);          // consecutive threads -> consecutive d
    const int bc = gid >> 11;                  // D = 2^11
    const int c  = bc & (NCHUNK - 1);
    const int b  = bc >> 2;

    const size_t base = (size_t)b * LIF_T * LIF_D + d;
    const float* __restrict__ xp = x + base;
    float* __restrict__ op = out + base;

    float v = 0.0f;
    const int t_out0 = c ? (LENC * c + WARM) : 0;
    const int len    = c ? LENC : LEN0;

    // ---- Warmup (chunks 1..3): 16 steps starting at t = 124c, no stores.
    // c is warp-uniform -> no divergence.
    if (c != 0) {
        const int tw0 = t_out0 - WARM;
        float xv[WARM];
        #pragma unroll
        for (int u = 0; u < WARM; u++)
            xv[u] = __ldg(xp + (size_t)(tw0 + u) * LIF_D);
        #pragma unroll
        for (int u = 0; u < WARM; u++) {
            float vn = lif_step(v, xv[u]);
            v = vn;
        }
    }

    // ---- Main loop: triple-buffered prefetch, distance 2 batches of UN=4.
    float b0[UN], b1[UN], b2[UN];
    #pragma unroll
    for (int u = 0; u < UN; u++)
        b0[u] = __ldg(xp + (size_t)(t_out0 + u) * LIF_D);
    #pragma unroll
    for (int u = 0; u < UN; u++)
        b1[u] = __ldg(xp + (size_t)(t_out0 + UN + u) * LIF_D);

    for (int tb = 0; tb < len; tb += UN) {
        const int t0 = t_out0 + tb;

        // 1) Prefetch batch tb + 2*UN (predicated at the tail).
        const bool has2 = (tb + 2 * UN < len);
        #pragma unroll
        for (int u = 0; u < UN; u++)
            b2[u] = has2 ? __ldg(xp + (size_t)(t0 + 2 * UN + u) * LIF_D) : 0.0f;

        // 2) Compute current batch from b0, store spikes.
        #pragma unroll
        for (int u = 0; u < UN; u++) {
            v = fmaf(0.5f, v, 0.5f * b0[u]);
            const float e = __expf(LIF_TH - v);
            const float s = __fdividef(1.0f, 1.0f + e);
            __stcs(op + (size_t)(t0 + u) * LIF_D, s);   // streaming write
            v = fmaf(-v, s, v);
        }

        // 3) Rotate buffers (register moves only).
        #pragma unroll
        for (int u = 0; u < UN; u++) { b0[u] = b1[u]; b1[u] = b2[u]; }
    }
}

extern "C" void kernel_launch(void* const* d_in, const int* in_sizes, int n_in,
                              void* d_out, int out_size) {
    const float* x = (const float*)d_in[0];
    float* out = (float*)d_out;

    const int n_threads_total = LIF_B * LIF_D * NCHUNK;   // 262,144
    const int threads = 256;
    const int blocks = n_threads_total / threads;         // 1024
    lif_kernel<<<blocks, threads>>>(x, out);
}